// round 1
// baseline (speedup 1.0000x reference)
#include <cuda_runtime.h>

#define S_GRID   14
#define NB       2            // boxes per cell (B)
#define NCLS     20           // C
#define N_EL     30           // B*5 + C
#define NBOX     16
#define NCELLS   (S_GRID * S_GRID)        // 196
#define IMG_FLOATS (NCELLS * N_EL)        // 5880
#define NTHREADS 256

__device__ double g_acc;

__global__ void yolo_init_kernel() { g_acc = 0.0; }

__device__ __forceinline__ float jaccard_corner(
    float ax1, float ay1, float ax2, float ay2,
    float bx1, float by1, float bx2, float by2)
{
    float ltx = fmaxf(ax1, bx1);
    float lty = fmaxf(ay1, by1);
    float rbx = fminf(ax2, bx2);
    float rby = fminf(ay2, by2);
    float wi = fmaxf(rbx - ltx, 0.0f);
    float hi = fmaxf(rby - lty, 0.0f);
    float inter = wi * hi;
    float area_a = (ax2 - ax1) * (ay2 - ay1);
    float area_b = (bx2 - bx1) * (by2 - by1);
    float uni = area_a + area_b - inter;
    if (uni == 0.0f) uni = 1.0f;
    return inter / uni;
}

__global__ __launch_bounds__(NTHREADS)
void yolo_loss_kernel(const float* __restrict__ pred,
                      const float* __restrict__ boxes,
                      const int*   __restrict__ classes)
{
    __shared__ float  sp[IMG_FLOATS];       // 23520 B: this image's prediction rows
    __shared__ float4 cellbox[NCELLS];      // (dx, dy, w, h) per occupied cell
    __shared__ int    cellcls[NCELLS];      // class id, -1 = empty
    __shared__ double ssum[NTHREADS];

    const int b   = blockIdx.x;
    const int tid = threadIdx.x;

    // ---- stage prediction tile (coalesced float4; 5880 % 4 == 0, base 16B-aligned) ----
    {
        const float4* src = reinterpret_cast<const float4*>(pred + (size_t)b * IMG_FLOATS);
        float4* dst = reinterpret_cast<float4*>(sp);
        #pragma unroll 2
        for (int i = tid; i < IMG_FLOATS / 4; i += NTHREADS) dst[i] = src[i];
    }
    if (tid < NCELLS) cellcls[tid] = -1;
    __syncthreads();

    // ---- encode 16 boxes into the cell table; serial loop => last write wins,
    //      matching the JAX scatter-set semantics over flat_idx order ----
    if (tid == 0) {
        const float cell = 1.0f / 14.0f;
        const float* bx = boxes + (size_t)b * NBOX * 4;
        const int*   cl = classes + (size_t)b * NBOX;
        for (int n = 0; n < NBOX; n++) {
            float x1 = bx[n * 4 + 0];
            float y1 = bx[n * 4 + 1];
            float x2 = bx[n * 4 + 2];
            float y2 = bx[n * 4 + 3];
            float w  = x2 - x1;
            float h  = y2 - y1;
            float cx = (x1 + x2) * 0.5f;
            float cy = (y1 + y2) * 0.5f;
            float vx = cx / cell;
            float vy = cy / cell;
            float ix = fminf(fmaxf(ceilf(vx) - 1.0f, 0.0f), (float)(S_GRID - 1));
            float iy = fminf(fmaxf(ceilf(vy) - 1.0f, 0.0f), (float)(S_GRID - 1));
            float dx = vx - ix;
            float dy = vy - iy;
            int ci = (int)iy * S_GRID + (int)ix;
            cellbox[ci] = make_float4(dx, dy, w, h);
            cellcls[ci] = cl[n];
        }
    }
    __syncthreads();

    // ---- one thread per grid cell (threads 196..255 idle for this phase) ----
    double acc = 0.0;
    if (tid < NCELLS) {
        const float* p = sp + tid * N_EL;
        int cls = cellcls[tid];
        if (cls < 0) {
            // noobj: target row is all zeros; conf channels 4 and 9
            float v = p[4] * p[4] + p[9] * p[9];
            acc = 0.5 * (double)v;
        } else {
            float4 tb = cellbox[tid];   // (dx, dy, w, h)

            // class loss over channels 10..29.
            // one-hot was placed at channel 9+cls => within [10,30): hot at cls-1
            // (cls == 0 lands on channel 9, outside this slice => all-zero target)
            float closs = 0.0f;
            #pragma unroll
            for (int c = 0; c < NCLS; c++) {
                float t = (cls == c + 1) ? 1.0f : 0.0f;
                float d = p[10 + c] - t;
                closs += d * d;
            }

            // corner-format jaccard applied verbatim to (dx,dy,w,h) rows;
            // both target boxes identical => responsible box = argmax over pred
            float iou0 = jaccard_corner(p[0], p[1], p[2], p[3], tb.x, tb.y, tb.z, tb.w);
            float iou1 = jaccard_corner(p[5], p[6], p[7], p[8], tb.x, tb.y, tb.z, tb.w);
            const float* bp = (iou1 > iou0) ? (p + 5) : p;   // ties -> box 0 (argmax first-max)

            float dconf = bp[4] - 1.0f;
            float contain = dconf * dconf;

            float d0 = bp[0] - tb.x;
            float d1 = bp[1] - tb.y;
            float d2 = sqrtf(bp[2]) - sqrtf(tb.z);
            float d3 = sqrtf(bp[3]) - sqrtf(tb.w);
            float loc = d0 * d0 + d1 * d1 + d2 * d2 + d3 * d3;

            acc = (double)(closs + contain + 5.0f * loc);
        }
    }
    ssum[tid] = acc;
    __syncthreads();

    #pragma unroll
    for (int s = NTHREADS / 2; s > 0; s >>= 1) {
        if (tid < s) ssum[tid] += ssum[tid + s];
        __syncthreads();
    }
    if (tid == 0) atomicAdd(&g_acc, ssum[0]);
}

__global__ void yolo_finish_kernel(float* out) { out[0] = (float)g_acc; }

extern "C" void kernel_launch(void* const* d_in, const int* in_sizes, int n_in,
                              void* d_out, int out_size)
{
    const float* pred    = (const float*)d_in[0];   // [4096, 5880]
    const float* boxes   = (const float*)d_in[1];   // [4096, 16, 4]
    const int*   classes = (const int*)d_in[2];     // [4096, 16]
    float* out = (float*)d_out;

    int batch = in_sizes[0] / IMG_FLOATS;   // 4096

    yolo_init_kernel<<<1, 1>>>();
    yolo_loss_kernel<<<batch, NTHREADS>>>(pred, boxes, classes);
    yolo_finish_kernel<<<1, 1>>>(out);
}

// round 2
// speedup vs baseline: 2.1551x; 2.1551x over previous
#include <cuda_runtime.h>

#define S_GRID 14
#define NCLS   20
#define N_EL   30
#define NBOX   16
#define NCELLS 196            // 14*14
#define IMG_FLOATS (NCELLS * N_EL)   // 5880
#define IMGS_PER_BLK 8
#define NTHREADS 256
#define CPL 7                 // ceil(196/32) cells per lane

__device__ double       g_acc;    // zero-initialized at module load; reset by last block
__device__ unsigned int g_count;

__device__ __forceinline__ float jac(float ax1, float ay1, float ax2, float ay2,
                                     float4 t)
{
    float ltx = fmaxf(ax1, t.x);
    float lty = fmaxf(ay1, t.y);
    float rbx = fminf(ax2, t.z);
    float rby = fminf(ay2, t.w);
    float wi = fmaxf(rbx - ltx, 0.0f);
    float hi = fmaxf(rby - lty, 0.0f);
    float inter = wi * hi;
    float area_a = (ax2 - ax1) * (ay2 - ay1);
    float area_b = (t.z - t.x) * (t.w - t.y);
    float uni = area_a + area_b - inter;
    if (uni == 0.0f) uni = 1.0f;
    return inter / uni;
}

__global__ __launch_bounds__(NTHREADS)
void yolo_kernel(const float* __restrict__ pred,
                 const float* __restrict__ boxes,
                 const int*   __restrict__ classes,
                 float* __restrict__ out,
                 int batch, int nblocks)
{
    __shared__ float4 sbox[IMGS_PER_BLK][NCELLS];
    __shared__ int    scls[IMGS_PER_BLK][NCELLS];
    __shared__ double bsum;

    const int tid  = threadIdx.x;
    const int w    = tid >> 5;
    const int lane = tid & 31;
    const int img  = blockIdx.x * IMGS_PER_BLK + w;

    if (tid == 0) bsum = 0.0;
    __syncthreads();

    if (img < batch) {
        // ---------- parallel encode: lanes 0..15, one box each ----------
        int   ci = -1 - lane;          // unique dummy so lanes 16..31 never collide
        float dx = 0.f, dy = 0.f, bw = 0.f, bh = 0.f;
        int   cls = 0;
        if (lane < NBOX) {
            float4 bb = reinterpret_cast<const float4*>(boxes)[img * NBOX + lane];
            cls = classes[img * NBOX + lane];
            bw = bb.z - bb.x;
            bh = bb.w - bb.y;
            float cx = (bb.x + bb.z) * 0.5f;
            float cy = (bb.y + bb.w) * 0.5f;
            const float cell = 1.0f / 14.0f;
            float vx = cx / cell;
            float vy = cy / cell;
            float ix = fminf(fmaxf(ceilf(vx) - 1.0f, 0.0f), 13.0f);
            float iy = fminf(fmaxf(ceilf(vy) - 1.0f, 0.0f), 13.0f);
            dx = vx - ix;
            dy = vy - iy;
            ci = (int)iy * S_GRID + (int)ix;
        }
        // init cell table (this warp's slice only)
        #pragma unroll
        for (int k = 0; k < CPL; k++) {
            int c = lane + 32 * k;
            if (c < NCELLS) scls[w][c] = -1;
        }
        __syncwarp();
        // last-write-wins: within each same-ci group, highest box index wins
        unsigned m = __match_any_sync(0xFFFFFFFFu, ci);
        if (lane < NBOX && (31 - __clz(m)) == lane) {
            sbox[w][ci] = make_float4(dx, dy, bw, bh);
            scls[w][ci] = cls;
        }
        __syncwarp();

        // ---------- score: 7 cells per lane, sparse conf prefetch ----------
        const float* p = pred + (size_t)img * IMG_FLOATS;
        float v4[CPL], v9[CPL];
        #pragma unroll
        for (int k = 0; k < CPL; k++) {
            int c = lane + 32 * k;
            if (c < NCELLS) {
                v4[k] = __ldg(p + c * N_EL + 4);
                v9[k] = __ldg(p + c * N_EL + 9);
            }
        }

        float facc = 0.0f;
        #pragma unroll
        for (int k = 0; k < CPL; k++) {
            int c = lane + 32 * k;
            if (c >= NCELLS) continue;
            int cl = scls[w][c];
            if (cl < 0) {
                facc += 0.5f * (v4[k] * v4[k] + v9[k] * v9[k]);
            } else {
                float4 tb = sbox[w][c];
                const float2* r2 = reinterpret_cast<const float2*>(p + c * N_EL);
                float2 a0 = r2[0], a1 = r2[1], a2 = r2[2], a3 = r2[3], a4 = r2[4];
                // pred box0 = (a0.x,a0.y,a1.x,a1.y) conf v4; box1 = (a2.y,a3.x,a3.y,a4.x) conf v9
                float iou0 = jac(a0.x, a0.y, a1.x, a1.y, tb);
                float iou1 = jac(a2.y, a3.x, a3.y, a4.x, tb);
                bool sel1 = iou1 > iou0;                 // tie -> box0 (argmax first-max)
                float bx  = sel1 ? a2.y : a0.x;
                float by  = sel1 ? a3.x : a0.y;
                float bw_ = sel1 ? a3.y : a1.x;
                float bh_ = sel1 ? a4.x : a1.y;
                float bc  = sel1 ? v9[k] : v4[k];

                // class loss over channels 10..29; one-hot at 9+cls => hot at cls-1
                float closs = 0.0f;
                #pragma unroll
                for (int i = 0; i < 10; i++) {
                    float2 cc = r2[5 + i];
                    float tx_ = (cl == 2 * i + 1) ? 1.0f : 0.0f;
                    float ty_ = (cl == 2 * i + 2) ? 1.0f : 0.0f;
                    float ex = cc.x - tx_;
                    float ey = cc.y - ty_;
                    closs += ex * ex + ey * ey;
                }

                float dconf = bc - 1.0f;
                float d0 = bx - tb.x;
                float d1 = by - tb.y;
                float d2 = sqrtf(bw_) - sqrtf(tb.z);
                float d3 = sqrtf(bh_) - sqrtf(tb.w);
                facc += closs + dconf * dconf
                      + 5.0f * (d0 * d0 + d1 * d1 + d2 * d2 + d3 * d3);
            }
        }

        // ---------- warp reduce, block accumulate ----------
        #pragma unroll
        for (int o = 16; o; o >>= 1)
            facc += __shfl_xor_sync(0xFFFFFFFFu, facc, o);
        if (lane == 0) atomicAdd(&bsum, (double)facc);
    }

    __syncthreads();
    if (tid == 0) {
        atomicAdd(&g_acc, bsum);
        __threadfence();
        unsigned done = atomicAdd(&g_count, 1u);
        if (done == (unsigned)(nblocks - 1)) {
            double total = atomicAdd(&g_acc, 0.0);   // coherent read of final sum
            out[0] = (float)total;
            g_acc = 0.0;          // reset for next replay (graph-safe, deterministic)
            g_count = 0u;
        }
    }
}

extern "C" void kernel_launch(void* const* d_in, const int* in_sizes, int n_in,
                              void* d_out, int out_size)
{
    const float* pred    = (const float*)d_in[0];   // [batch, 5880]
    const float* boxes   = (const float*)d_in[1];   // [batch, 16, 4]
    const int*   classes = (const int*)d_in[2];     // [batch, 16]
    float* out = (float*)d_out;

    int batch   = in_sizes[0] / IMG_FLOATS;
    int nblocks = (batch + IMGS_PER_BLK - 1) / IMGS_PER_BLK;

    yolo_kernel<<<nblocks, NTHREADS>>>(pred, boxes, classes, out, batch, nblocks);
}